// round 13
// baseline (speedup 1.0000x reference)
#include <cuda_runtime.h>

#define NUM_FACES 13776
#define MAXC 8
#define EPSF 1e-8f
#define CAP0 512                      // phase-A scan depth (16 chunks)
#define SEGW 512                      // steal segment width
#define NSEG 26                       // (13824-512)/512
#define PADF 13824                    // CAP0 + NSEG*SEGW, sentinel-padded
#define CAPD 1024                     // max deep-row slots
#define GRID 148                      // persistent: 1 block/SM, all resident
#define TPB 1024
#define NWARPS_C (GRID * (TPB / 32))  // 4736

// ---- device scratch (static; no runtime allocations) ----
__device__ float4 g_bb0[PADF];        // (lo.xyz, bits(i0|i1<<16))
__device__ float4 g_bb1[PADF];        // (hi.xyz, bits(i2))
__device__ int    g_cnt[NUM_FACES];   // deep rows: partial count at publish
__device__ int    g_pairs[NUM_FACES * MAXC];   // deep rows: partial js
__device__ int    g_deep[CAPD];       // slot -> row+1 (0 = not yet visible)
__device__ int    g_rowseg[CAPD];     // segment claim counter per slot
__device__ int    g_segdone[CAPD];    // segments completed per slot
__device__ int    g_seg_cnt[CAPD * NSEG];
__device__ int    g_seg_js[CAPD * NSEG * MAXC];
__device__ int    g_ndeep;            // deep slots reserved
__device__ int    g_warps_scanned;    // warps done with phase A (== NWARPS_C)
__device__ int    g_rows_merged;      // deep rows merged
__device__ double g_accum;            // self-resetting
__device__ unsigned g_done;           // self-resetting

// ---------------------------------------------------------------------------
// Kernel 1: 4 lanes per face -> AABB + packed ids; sentinels; zero steal state
// ---------------------------------------------------------------------------
__global__ void __launch_bounds__(256) setup_kernel(
        const float* __restrict__ verts, const int* __restrict__ faces) {
    int gt = (int)blockIdx.x * 256 + threadIdx.x;   // 216*256 = 55296 = 4*PADF
    int f = gt >> 2;
    int l = gt & 3;

    if (gt < CAPD) { g_deep[gt] = 0; g_rowseg[gt] = 0; g_segdone[gt] = 0; }
    if (gt == 0) { g_ndeep = 0; g_warps_scanned = 0; g_rows_merged = 0; }

    if (f >= NUM_FACES) {               // sentinel columns: never overlap
        if (f < PADF && l == 0) {
            g_bb0[f] = make_float4(1e30f, 1e30f, 1e30f, __int_as_float(-1));
            g_bb1[f] = make_float4(-1e30f, -1e30f, -1e30f, __int_as_float(-1));
        }
        return;
    }

    int comp = (l < 2) ? l : 2;         // lane 3 duplicates lane 2
    int idx = faces[3 * f + comp];
    float x = verts[3 * idx + 0];
    float y = verts[3 * idx + 1];
    float z = verts[3 * idx + 2];

    float mnx = x, mny = y, mnz = z, mxx = x, mxy = y, mxz = z;
#pragma unroll
    for (int off = 1; off <= 2; off <<= 1) {        // quad reduction
        mnx = fminf(mnx, __shfl_xor_sync(0xffffffffu, mnx, off));
        mny = fminf(mny, __shfl_xor_sync(0xffffffffu, mny, off));
        mnz = fminf(mnz, __shfl_xor_sync(0xffffffffu, mnz, off));
        mxx = fmaxf(mxx, __shfl_xor_sync(0xffffffffu, mxx, off));
        mxy = fmaxf(mxy, __shfl_xor_sync(0xffffffffu, mxy, off));
        mxz = fmaxf(mxz, __shfl_xor_sync(0xffffffffu, mxz, off));
    }
    int i1 = __shfl_xor_sync(0xffffffffu, idx, 1);
    int i2 = __shfl_xor_sync(0xffffffffu, idx, 2);
    if (l == 0) {
        g_bb0[f] = make_float4(mnx, mny, mnz, __int_as_float(idx | (i1 << 16)));
        g_bb1[f] = make_float4(mxx, mxy, mxz, __int_as_float(i2));
    }
}

struct Tri { float3 v0, v1, v2; };

__device__ __forceinline__ float3 vert3(const float* __restrict__ v, int i) {
    return make_float3(v[3 * i], v[3 * i + 1], v[3 * i + 2]);
}

// Cone-field penalty of src triangle A at the 3 verts of P. SIGMA=0.5 -> *2.
__device__ __forceinline__ float cone_pen(const Tri& A, const Tri& P) {
    float e0x = A.v1.x - A.v0.x, e0y = A.v1.y - A.v0.y, e0z = A.v1.z - A.v0.z;
    float e1x = A.v2.x - A.v0.x, e1y = A.v2.y - A.v0.y, e1z = A.v2.z - A.v0.z;
    float nx = e0y * e1z - e0z * e1y;
    float ny = e0z * e1x - e0x * e1z;
    float nz = e0x * e1y - e0y * e1x;
    float nn = sqrtf(nx * nx + ny * ny + nz * nz);
    float inv = 1.0f / (nn + EPSF);
    nx *= inv; ny *= inv; nz *= inv;
    float cx = (A.v0.x + A.v1.x + A.v2.x) * (1.0f / 3.0f);
    float cy = (A.v0.y + A.v1.y + A.v2.y) * (1.0f / 3.0f);
    float cz = (A.v0.z + A.v1.z + A.v2.z) * (1.0f / 3.0f);
    const float3* pv = &P.v0;
    float pen = 0.0f;
#pragma unroll
    for (int v = 0; v < 3; v++) {
        float ux = pv[v].x - cx, uy = pv[v].y - cy, uz = pv[v].z - cz;
        float h = ux * nx + uy * ny + uz * nz;
        float wx = ux - h * nx, wy = uy - h * ny, wz = uz - h * nz;
        float r = sqrtf(wx * wx + wy * wy + wz * wz);
        float radial = fmaxf(1.0f - r * 2.0f, 0.0f);
        float depth = fmaxf(-h, 0.0f) + fmaxf(h, 0.0f) * __expf(-h * 2.0f);
        float phi = radial * depth;
        pen += phi * phi;
    }
    return pen;
}

// AABB overlap + shared-vertex exclusion (exact reference semantics)
__device__ __forceinline__ bool pair_ok(const float4& bmin, const float4& bmax,
                                        int rf0, int rf1, int rf2,
                                        const float4& ja, const float4& jb) {
    bool ok = (bmin.x <= jb.x) && (ja.x <= bmax.x) &&
              (bmin.y <= jb.y) && (ja.y <= bmax.y) &&
              (bmin.z <= jb.z) && (ja.z <= bmax.z);
    if (ok) {
        int jp = __float_as_int(ja.w);
        int jf0 = jp & 0xFFFF, jf1 = jp >> 16;
        int jf2 = __float_as_int(jb.w);
        bool share = (rf0 == jf0) | (rf0 == jf1) | (rf0 == jf2) |
                     (rf1 == jf0) | (rf1 == jf1) | (rf1 == jf2) |
                     (rf2 == jf0) | (rf2 == jf1) | (rf2 == jf2);
        ok = !share;
    }
    return ok;
}

// 16-lane pair evaluation: lanes 0..15 -> (pair, direction). All-lane sum.
__device__ __forceinline__ float eval_pairs(const float* __restrict__ verts,
                                            int rf0, int rf1, int rf2,
                                            const int* jlist, int cnt, int lane) {
    float pen = 0.0f;
    int pairIdx = lane >> 1;
    if (lane < 16 && pairIdx < cnt) {
        int j = jlist[pairIdx];
        int jp = __float_as_int(g_bb0[j].w);
        int jf2 = __float_as_int(g_bb1[j].w);
        Tri R, J;
        R.v0 = vert3(verts, rf0); R.v1 = vert3(verts, rf1); R.v2 = vert3(verts, rf2);
        J.v0 = vert3(verts, jp & 0xFFFF); J.v1 = vert3(verts, jp >> 16);
        J.v2 = vert3(verts, jf2);
        pen = (lane & 1) ? cone_pen(J, R) : cone_pen(R, J);
    }
#pragma unroll
    for (int off = 16; off > 0; off >>= 1)
        pen += __shfl_xor_sync(0xffffffffu, pen, off);
    return pen;
}

// ---------------------------------------------------------------------------
// Kernel 2 (PERSISTENT, all blocks resident): warp-per-row scan (<=512 cols)
// + barrier-free deep-row segment stealing. Exit conditions are monotonic
// globals; every warp of every resident block eventually satisfies them.
// ---------------------------------------------------------------------------
__global__ void __launch_bounds__(TPB, 1) collide_kernel(
        const float* __restrict__ verts, float* __restrict__ out) {
    __shared__ int    s_j[TPB / 32][MAXC];
    __shared__ double s_bsum;

    int tid = threadIdx.x;
    int lane = tid & 31;
    int wwid = tid >> 5;
    int gwarp = (int)blockIdx.x * (TPB / 32) + wwid;
    unsigned below = (1u << lane) - 1u;
    if (tid == 0) s_bsum = 0.0;
    __syncthreads();
    double mysum = 0.0;

    // ---- Phase A: rows strided across all warps ---------------------------
    for (int row = gwarp; row < NUM_FACES; row += NWARPS_C) {
        float4 bmin = g_bb0[row];
        float4 bmax = g_bb1[row];
        int rp = __float_as_int(bmin.w);
        int rf0 = rp & 0xFFFF, rf1 = rp >> 16;
        int rf2 = __float_as_int(bmax.w);

        int found = 0;
        for (int base = 0; base < CAP0 && found < MAXC; base += 32) {
            int j = base + lane;
            bool ok = pair_ok(bmin, bmax, rf0, rf1, rf2, g_bb0[j], g_bb1[j]);
            unsigned m = __ballot_sync(0xffffffffu, ok);
            int rank = found + __popc(m & below);
            if (ok && rank < MAXC) s_j[wwid][rank] = j;
            found += __popc(m);
        }
        __syncwarp();

        if (found >= MAXC) {
            mysum += (double)eval_pairs(verts, rf0, rf1, rf2, s_j[wwid],
                                        MAXC, lane);
        } else {
            // deep row: publish partials + slot; segments become stealable
            if (lane < found) g_pairs[(row << 3) + lane] = s_j[wwid][lane];
            int slot = -1;
            if (lane == 0) {
                g_cnt[row] = found;
                __threadfence();
                slot = atomicAdd(&g_ndeep, 1);
                if (slot < CAPD) g_deep[slot] = row + 1;   // flag last
            }
            slot = __shfl_sync(0xffffffffu, slot, 0);
            if (slot >= CAPD) {        // overflow fallback: finish serially
                for (int base = CAP0; base < PADF && found < MAXC; base += 32) {
                    int j = base + lane;
                    bool ok = pair_ok(bmin, bmax, rf0, rf1, rf2,
                                      g_bb0[j], g_bb1[j]);
                    unsigned m = __ballot_sync(0xffffffffu, ok);
                    int rank = found + __popc(m & below);
                    if (ok && rank < MAXC) s_j[wwid][rank] = j;
                    found += __popc(m);
                }
                __syncwarp();
                mysum += (double)eval_pairs(verts, rf0, rf1, rf2, s_j[wwid],
                                            min(found, MAXC), lane);
            }
        }
        __syncwarp();
    }
    if (lane == 0) atomicAdd(&g_warps_scanned, 1);

    // ---- Phase B: steal deep-row segments (all warps resident) ------------
    for (;;) {
        int ws = *(volatile int*)&g_warps_scanned;
        int nd = *(volatile int*)&g_ndeep; nd = min(nd, CAPD);
        int merged = *(volatile int*)&g_rows_merged;
        bool did = false;

        if (merged < nd) {
            for (int slot = 0; slot < nd; slot++) {
                if (*(volatile int*)&g_segdone[slot] >= NSEG) continue;
                int row1 = *(volatile int*)&g_deep[slot];
                if (row1 == 0) { did = true; continue; }   // publish in flight
                int drow = row1 - 1;
                for (;;) {
                    int seg = 0;
                    if (lane == 0) seg = atomicAdd(&g_rowseg[slot], 1);
                    seg = __shfl_sync(0xffffffffu, seg, 0);
                    if (seg >= NSEG) break;
                    did = true;

                    float4 dmin = g_bb0[drow];
                    float4 dmax = g_bb1[drow];
                    int dp = __float_as_int(dmin.w);
                    int df0 = dp & 0xFFFF, df1 = dp >> 16;
                    int df2 = __float_as_int(dmax.w);
                    int item = slot * NSEG + seg;
                    int sf = 0;
                    int start = CAP0 + seg * SEGW;
                    for (int base = start; base < start + SEGW && sf < MAXC;
                         base += 32) {
                        int j = base + lane;
                        bool ok = pair_ok(dmin, dmax, df0, df1, df2,
                                          g_bb0[j], g_bb1[j]);
                        unsigned m = __ballot_sync(0xffffffffu, ok);
                        int rank = sf + __popc(m & below);
                        if (ok && rank < MAXC) g_seg_js[(item << 3) + rank] = j;
                        sf += __popc(m);
                    }
                    if (lane == 0) g_seg_cnt[item] = min(sf, MAXC);
                    __threadfence();
                    int d = 0;
                    if (lane == 0) d = atomicAdd(&g_segdone[slot], 1);
                    d = __shfl_sync(0xffffffffu, d, 0);

                    if (d == NSEG - 1) {       // last finisher merges + evals
                        __threadfence();
                        int m2 = 0;
                        if (lane == 0) {
                            int c0 = g_cnt[drow];
                            for (int k = 0; k < c0; k++)
                                s_j[wwid][m2++] = g_pairs[(drow << 3) + k];
                            for (int s = 0; s < NSEG && m2 < MAXC; s++) {
                                int it = slot * NSEG + s;
                                int c = g_seg_cnt[it];
                                for (int k = 0; k < c && m2 < MAXC; k++)
                                    s_j[wwid][m2++] = g_seg_js[(it << 3) + k];
                            }
                        }
                        __syncwarp();
                        m2 = __shfl_sync(0xffffffffu, m2, 0);
                        mysum += (double)eval_pairs(verts, df0, df1, df2,
                                                    s_j[wwid], m2, lane);
                        if (lane == 0) atomicAdd(&g_rows_merged, 1);
                        __syncwarp();
                    }
                }
            }
        }

        if (ws == NWARPS_C) {
            int ndf = *(volatile int*)&g_ndeep; ndf = min(ndf, CAPD);
            if (*(volatile int*)&g_rows_merged >= ndf) break;
        }
        if (!did) __nanosleep(128);
    }

    if (lane == 0 && mysum != 0.0) atomicAdd(&s_bsum, mysum);
    __syncthreads();

    // fused finalize: last-exiting block writes output + resets state
    if (tid == 0) {
        if (s_bsum != 0.0) atomicAdd(&g_accum, s_bsum);
        __threadfence();
        unsigned old = atomicAdd(&g_done, 1u);
        if (old == GRID - 1) {
            g_done = 0;
            unsigned long long bits =
                atomicExch((unsigned long long*)&g_accum, 0ULL);
            out[0] = (float)__longlong_as_double(bits);  // weight = 1.0
        }
    }
}

extern "C" void kernel_launch(void* const* d_in, const int* in_sizes, int n_in,
                              void* d_out, int out_size) {
    const float* verts = (const float*)d_in[0];
    const int*   faces = (const int*)d_in[1];
    float*       out   = (float*)d_out;

    setup_kernel<<<(4 * PADF) / 256, 256>>>(verts, faces);
    collide_kernel<<<GRID, TPB>>>(verts, out);
}

// round 14
// speedup vs baseline: 1.6187x; 1.6187x over previous
#include <cuda_runtime.h>

#define NUM_FACES 13776
#define MAXC 8
#define EPSF 1e-8f
#define PADF 13792                    // pad to multiple of 32 (16 sentinels)
#define K2_BLOCKS (NUM_FACES / 8)     // 1722 blocks, 8 warps, warp-per-row

// ---- device scratch (static; no runtime allocations) ----
__device__ float4 g_bb0[PADF];        // (lo.xyz, bits(i0|i1<<16))
__device__ float4 g_bb1[PADF];        // (hi.xyz, bits(i2))
__device__ float4 g_tv[NUM_FACES*3];  // per-face vertices (xyz, -)
__device__ float4 g_n[NUM_FACES];     // per-face unit normal (xyz, -)
__device__ float4 g_c[NUM_FACES];     // per-face centroid (xyz, -)
__device__ double g_accum;            // self-resetting
__device__ unsigned g_done;           // self-resetting

// ---------------------------------------------------------------------------
// Kernel 1: thread-per-face. AABB + packed ids + verts + normal + centroid.
// The normal/centroid math here replaces its recomputation in EVERY pair eval
// (13776 times instead of ~220k).
// ---------------------------------------------------------------------------
__global__ void __launch_bounds__(128) setup_kernel(
        const float* __restrict__ verts, const int* __restrict__ faces) {
    int f = (int)blockIdx.x * 128 + threadIdx.x;   // 108*128 = 13824 >= PADF
    if (f >= PADF) return;
    if (f >= NUM_FACES) {                           // sentinel: never overlaps
        g_bb0[f] = make_float4(1e30f, 1e30f, 1e30f, __int_as_float(-1));
        g_bb1[f] = make_float4(-1e30f, -1e30f, -1e30f, __int_as_float(-1));
        return;
    }

    int i0 = faces[3 * f + 0];
    int i1 = faces[3 * f + 1];
    int i2 = faces[3 * f + 2];

    float x0 = verts[3*i0], y0 = verts[3*i0+1], z0 = verts[3*i0+2];
    float x1 = verts[3*i1], y1 = verts[3*i1+1], z1 = verts[3*i1+2];
    float x2 = verts[3*i2], y2 = verts[3*i2+1], z2 = verts[3*i2+2];

    g_tv[f*3+0] = make_float4(x0, y0, z0, 0.f);
    g_tv[f*3+1] = make_float4(x1, y1, z1, 0.f);
    g_tv[f*3+2] = make_float4(x2, y2, z2, 0.f);

    // AABB
    float mnx = fminf(x0, fminf(x1, x2)), mxx = fmaxf(x0, fmaxf(x1, x2));
    float mny = fminf(y0, fminf(y1, y2)), mxy = fmaxf(y0, fmaxf(y1, y2));
    float mnz = fminf(z0, fminf(z1, z2)), mxz = fmaxf(z0, fmaxf(z1, z2));
    g_bb0[f] = make_float4(mnx, mny, mnz, __int_as_float(i0 | (i1 << 16)));
    g_bb1[f] = make_float4(mxx, mxy, mxz, __int_as_float(i2));

    // unit normal (e0 x e1, normalized with EPS) + centroid
    float e0x = x1-x0, e0y = y1-y0, e0z = z1-z0;
    float e1x = x2-x0, e1y = y2-y0, e1z = z2-z0;
    float nx = e0y*e1z - e0z*e1y;
    float ny = e0z*e1x - e0x*e1z;
    float nz = e0x*e1y - e0y*e1x;
    float inv = 1.0f / (sqrtf(nx*nx + ny*ny + nz*nz) + EPSF);
    g_n[f] = make_float4(nx*inv, ny*inv, nz*inv, 0.f);
    g_c[f] = make_float4((x0+x1+x2)*(1.0f/3.0f),
                         (y0+y1+y2)*(1.0f/3.0f),
                         (z0+z1+z2)*(1.0f/3.0f), 0.f);
}

// Cone-field penalty with precomputed (n, c) of src, at pts (p0,p1,p2).
// SIGMA = 0.5 -> /SIGMA == *2 exact.
__device__ __forceinline__ float cone_pen_nc(float4 n, float4 c,
                                             float4 p0, float4 p1, float4 p2) {
    float pen = 0.0f;
#pragma unroll
    for (int v = 0; v < 3; v++) {
        float4 p = (v == 0) ? p0 : (v == 1) ? p1 : p2;
        float ux = p.x - c.x, uy = p.y - c.y, uz = p.z - c.z;
        float h = ux*n.x + uy*n.y + uz*n.z;
        float wx = ux - h*n.x, wy = uy - h*n.y, wz = uz - h*n.z;
        float r = sqrtf(wx*wx + wy*wy + wz*wz);
        float radial = fmaxf(1.0f - r*2.0f, 0.0f);
        float depth = fmaxf(-h, 0.0f) + fmaxf(h, 0.0f) * __expf(-h*2.0f);
        float phi = radial * depth;
        pen += phi * phi;
    }
    return pen;
}

// ---------------------------------------------------------------------------
// Kernel 2: warp-per-row early-exit ballot scan (first 8 ascending == stable
// top_k) + 16-lane eval with precomputed normals, fused finalize.
// ---------------------------------------------------------------------------
__global__ void __launch_bounds__(256) collide_kernel(float* __restrict__ out) {
    __shared__ int    s_j[8][MAXC];
    __shared__ double s_bsum;

    int tid = threadIdx.x;
    int lane = tid & 31;
    int wwid = tid >> 5;
    int row = (int)blockIdx.x * 8 + wwid;          // 1722*8 = 13776 exactly
    unsigned below = (1u << lane) - 1u;
    if (tid == 0) s_bsum = 0.0;

    float4 bmin = g_bb0[row];
    float4 bmax = g_bb1[row];
    int rp = __float_as_int(bmin.w);
    int rf0 = rp & 0xFFFF, rf1 = rp >> 16;
    int rf2 = __float_as_int(bmax.w);

    // serial ballot scan, early exit; typical row: 1 chunk, worst ~7
    int found = 0;
    for (int base = 0; base < PADF && found < MAXC; base += 32) {
        int j = base + lane;
        float4 ja = g_bb0[j];
        float4 jb = g_bb1[j];
        bool ok = (bmin.x <= jb.x) && (ja.x <= bmax.x) &&
                  (bmin.y <= jb.y) && (ja.y <= bmax.y) &&
                  (bmin.z <= jb.z) && (ja.z <= bmax.z);
        if (ok) {
            int jp = __float_as_int(ja.w);
            int jf0 = jp & 0xFFFF, jf1 = jp >> 16;
            int jf2 = __float_as_int(jb.w);
            bool share = (rf0 == jf0) | (rf0 == jf1) | (rf0 == jf2) |
                         (rf1 == jf0) | (rf1 == jf1) | (rf1 == jf2) |
                         (rf2 == jf0) | (rf2 == jf1) | (rf2 == jf2);
            ok = !share;
        }
        unsigned m = __ballot_sync(0xffffffffu, ok);
        int rank = found + __popc(m & below);
        if (ok && rank < MAXC) s_j[wwid][rank] = j;
        found += __popc(m);
    }
    if (found > MAXC) found = MAXC;
    __syncwarp();

    // narrow phase: lanes 0..15 -> (pair 0..7) x (direction 0..1)
    float pen = 0.0f;
    int pairIdx = lane >> 1;
    if (lane < 16 && pairIdx < found) {
        int j = s_j[wwid][pairIdx];
        int srcF = (lane & 1) ? j : row;           // field-generating tri
        int ptsF = (lane & 1) ? row : j;           // query vertices
        float4 n = g_n[srcF];
        float4 c = g_c[srcF];
        float4 p0 = g_tv[ptsF*3+0];
        float4 p1 = g_tv[ptsF*3+1];
        float4 p2 = g_tv[ptsF*3+2];
        pen = cone_pen_nc(n, c, p0, p1, p2);
    }
#pragma unroll
    for (int off = 16; off > 0; off >>= 1)
        pen += __shfl_xor_sync(0xffffffffu, pen, off);
    if (lane == 0 && pen != 0.0f) atomicAdd(&s_bsum, (double)pen);
    __syncthreads();

    // fused finalize: last-arriving block writes output + resets state
    if (tid == 0) {
        if (s_bsum != 0.0) atomicAdd(&g_accum, s_bsum);
        __threadfence();
        unsigned old = atomicAdd(&g_done, 1u);
        if (old == K2_BLOCKS - 1) {
            g_done = 0;                             // reset for graph replay
            unsigned long long bits =
                atomicExch((unsigned long long*)&g_accum, 0ULL);
            out[0] = (float)__longlong_as_double(bits);  // weight = 1.0
        }
    }
}

extern "C" void kernel_launch(void* const* d_in, const int* in_sizes, int n_in,
                              void* d_out, int out_size) {
    const float* verts = (const float*)d_in[0];
    const int*   faces = (const int*)d_in[1];
    float*       out   = (float*)d_out;

    setup_kernel<<<(PADF + 127) / 128, 128>>>(verts, faces);
    collide_kernel<<<K2_BLOCKS, 256>>>(out);
}

// round 15
// speedup vs baseline: 2.0046x; 1.2384x over previous
#include <cuda_runtime.h>

#define NUM_FACES 13776
#define MAXC 8
#define EPSF 1e-8f
#define PADF 13792                    // pad to multiple of 32 (16 sentinels)
#define K2_BLOCKS (NUM_FACES / 16)    // 861 blocks, 8 warps, 2 rows per warp

// ---- device scratch (static; no runtime allocations) ----
__device__ float4 g_bb0[PADF];        // (lo.xyz, bits(i0|i1<<16))
__device__ float4 g_bb1[PADF];        // (hi.xyz, bits(i2))
__device__ float4 g_tv[NUM_FACES*3];  // per-face vertices (xyz, -)
__device__ float4 g_n[NUM_FACES];     // per-face unit normal (xyz, -)
__device__ float4 g_c[NUM_FACES];     // per-face centroid (xyz, -)
__device__ double g_accum;            // self-resetting
__device__ unsigned g_done;           // self-resetting

// ---------------------------------------------------------------------------
// Kernel 1: thread-per-face. AABB + packed ids + verts + normal + centroid.
// ---------------------------------------------------------------------------
__global__ void __launch_bounds__(128) setup_kernel(
        const float* __restrict__ verts, const int* __restrict__ faces) {
    int f = (int)blockIdx.x * 128 + threadIdx.x;   // 108*128 = 13824 >= PADF
    if (f >= PADF) return;
    if (f >= NUM_FACES) {                           // sentinel: never overlaps
        g_bb0[f] = make_float4(1e30f, 1e30f, 1e30f, __int_as_float(-1));
        g_bb1[f] = make_float4(-1e30f, -1e30f, -1e30f, __int_as_float(-1));
        return;
    }

    int i0 = faces[3 * f + 0];
    int i1 = faces[3 * f + 1];
    int i2 = faces[3 * f + 2];

    float x0 = verts[3*i0], y0 = verts[3*i0+1], z0 = verts[3*i0+2];
    float x1 = verts[3*i1], y1 = verts[3*i1+1], z1 = verts[3*i1+2];
    float x2 = verts[3*i2], y2 = verts[3*i2+1], z2 = verts[3*i2+2];

    g_tv[f*3+0] = make_float4(x0, y0, z0, 0.f);
    g_tv[f*3+1] = make_float4(x1, y1, z1, 0.f);
    g_tv[f*3+2] = make_float4(x2, y2, z2, 0.f);

    float mnx = fminf(x0, fminf(x1, x2)), mxx = fmaxf(x0, fmaxf(x1, x2));
    float mny = fminf(y0, fminf(y1, y2)), mxy = fmaxf(y0, fmaxf(y1, y2));
    float mnz = fminf(z0, fminf(z1, z2)), mxz = fmaxf(z0, fmaxf(z1, z2));
    g_bb0[f] = make_float4(mnx, mny, mnz, __int_as_float(i0 | (i1 << 16)));
    g_bb1[f] = make_float4(mxx, mxy, mxz, __int_as_float(i2));

    float e0x = x1-x0, e0y = y1-y0, e0z = z1-z0;
    float e1x = x2-x0, e1y = y2-y0, e1z = z2-z0;
    float nx = e0y*e1z - e0z*e1y;
    float ny = e0z*e1x - e0x*e1z;
    float nz = e0x*e1y - e0y*e1x;
    float inv = 1.0f / (sqrtf(nx*nx + ny*ny + nz*nz) + EPSF);
    g_n[f] = make_float4(nx*inv, ny*inv, nz*inv, 0.f);
    g_c[f] = make_float4((x0+x1+x2)*(1.0f/3.0f),
                         (y0+y1+y2)*(1.0f/3.0f),
                         (z0+z1+z2)*(1.0f/3.0f), 0.f);
}

// Cone-field penalty with precomputed (n, c). SIGMA=0.5 -> *2 exact.
__device__ __forceinline__ float cone_pen_nc(float4 n, float4 c,
                                             float4 p0, float4 p1, float4 p2) {
    float pen = 0.0f;
#pragma unroll
    for (int v = 0; v < 3; v++) {
        float4 p = (v == 0) ? p0 : (v == 1) ? p1 : p2;
        float ux = p.x - c.x, uy = p.y - c.y, uz = p.z - c.z;
        float h = ux*n.x + uy*n.y + uz*n.z;
        float wx = ux - h*n.x, wy = uy - h*n.y, wz = uz - h*n.z;
        float r = sqrtf(wx*wx + wy*wy + wz*wz);
        float radial = fmaxf(1.0f - r*2.0f, 0.0f);
        float depth = fmaxf(-h, 0.0f) + fmaxf(h, 0.0f) * __expf(-h*2.0f);
        float phi = radial * depth;
        pen += phi * phi;
    }
    return pen;
}

// shared-vertex test given packed ids
__device__ __forceinline__ bool share_ids(int rf0, int rf1, int rf2,
                                          int jp, int jf2) {
    int jf0 = jp & 0xFFFF, jf1 = jp >> 16;
    return (rf0 == jf0) | (rf0 == jf1) | (rf0 == jf2) |
           (rf1 == jf0) | (rf1 == jf1) | (rf1 == jf2) |
           (rf2 == jf0) | (rf2 == jf1) | (rf2 == jf2);
}

// ---------------------------------------------------------------------------
// Kernel 2: TWO rows per warp. Each scan chunk loads 32 column AABBs once
// and tests both rows (halved load traffic per row); eval uses all 32 lanes
// (16 pair-slots per row). First-8-ascending per row == stable top_k.
// ---------------------------------------------------------------------------
__global__ void __launch_bounds__(256) collide_kernel(float* __restrict__ out) {
    __shared__ int    s_j[8][16];     // [warp][pair + 8*rowsel]
    __shared__ double s_bsum;

    int tid = threadIdx.x;
    int lane = tid & 31;
    int wwid = tid >> 5;
    int row0 = ((int)blockIdx.x * 8 + wwid) * 2;   // 861*8*2 = 13776 exactly
    int row1 = row0 + 1;
    unsigned below = (1u << lane) - 1u;
    if (tid == 0) s_bsum = 0.0;

    float4 amin = g_bb0[row0], amax = g_bb1[row0];
    float4 bmin = g_bb0[row1], bmax = g_bb1[row1];
    int ap = __float_as_int(amin.w);
    int af0 = ap & 0xFFFF, af1 = ap >> 16, af2 = __float_as_int(amax.w);
    int bp = __float_as_int(bmin.w);
    int bf0 = bp & 0xFFFF, bf1 = bp >> 16, bf2 = __float_as_int(bmax.w);

    // dual-row serial ballot scan with shared column loads, early exit
    int found0 = 0, found1 = 0;
    for (int base = 0; base < PADF && (found0 < MAXC || found1 < MAXC);
         base += 32) {
        int j = base + lane;
        float4 ja = g_bb0[j];
        float4 jb = g_bb1[j];
        int jp = __float_as_int(ja.w);
        int jf2 = __float_as_int(jb.w);

        bool ok0 = (amin.x <= jb.x) && (ja.x <= amax.x) &&
                   (amin.y <= jb.y) && (ja.y <= amax.y) &&
                   (amin.z <= jb.z) && (ja.z <= amax.z);
        if (ok0) ok0 = !share_ids(af0, af1, af2, jp, jf2);
        bool ok1 = (bmin.x <= jb.x) && (ja.x <= bmax.x) &&
                   (bmin.y <= jb.y) && (ja.y <= bmax.y) &&
                   (bmin.z <= jb.z) && (ja.z <= bmax.z);
        if (ok1) ok1 = !share_ids(bf0, bf1, bf2, jp, jf2);

        unsigned m0 = __ballot_sync(0xffffffffu, ok0);
        unsigned m1 = __ballot_sync(0xffffffffu, ok1);
        int rank0 = found0 + __popc(m0 & below);
        int rank1 = found1 + __popc(m1 & below);
        if (ok0 && rank0 < MAXC) s_j[wwid][rank0] = j;
        if (ok1 && rank1 < MAXC) s_j[wwid][8 + rank1] = j;
        found0 += __popc(m0);
        found1 += __popc(m1);
    }
    if (found0 > MAXC) found0 = MAXC;
    if (found1 > MAXC) found1 = MAXC;
    __syncwarp();

    // narrow phase: 32 lanes -> (row l>>4) x (pair (l&15)>>1) x (dir l&1)
    int rowsel = lane >> 4;
    int l = lane & 15;
    int pairIdx = l >> 1;
    int cnt = rowsel ? found1 : found0;
    float pen = 0.0f;
    if (pairIdx < cnt) {
        int row = rowsel ? row1 : row0;
        int j = s_j[wwid][(rowsel << 3) + pairIdx];
        int srcF = (l & 1) ? j : row;              // field-generating tri
        int ptsF = (l & 1) ? row : j;              // query vertices
        float4 n = g_n[srcF];
        float4 c = g_c[srcF];
        float4 p0 = g_tv[ptsF*3+0];
        float4 p1 = g_tv[ptsF*3+1];
        float4 p2 = g_tv[ptsF*3+2];
        pen = cone_pen_nc(n, c, p0, p1, p2);
    }
#pragma unroll
    for (int off = 16; off > 0; off >>= 1)
        pen += __shfl_xor_sync(0xffffffffu, pen, off);
    if (lane == 0 && pen != 0.0f) atomicAdd(&s_bsum, (double)pen);
    __syncthreads();

    // fused finalize: last-arriving block writes output + resets state
    if (tid == 0) {
        if (s_bsum != 0.0) atomicAdd(&g_accum, s_bsum);
        __threadfence();
        unsigned old = atomicAdd(&g_done, 1u);
        if (old == K2_BLOCKS - 1) {
            g_done = 0;                             // reset for graph replay
            unsigned long long bits =
                atomicExch((unsigned long long*)&g_accum, 0ULL);
            out[0] = (float)__longlong_as_double(bits);  // weight = 1.0
        }
    }
}

extern "C" void kernel_launch(void* const* d_in, const int* in_sizes, int n_in,
                              void* d_out, int out_size) {
    const float* verts = (const float*)d_in[0];
    const int*   faces = (const int*)d_in[1];
    float*       out   = (float*)d_out;

    setup_kernel<<<(PADF + 127) / 128, 128>>>(verts, faces);
    collide_kernel<<<K2_BLOCKS, 256>>>(out);
}